// round 16
// baseline (speedup 1.0000x reference)
#include <cuda_runtime.h>
#include <cuda_bf16.h>
#include <mma.h>
#include <math.h>
#include <stdint.h>

using namespace nvcuda;

// ---------------------------------------------------------------------------
// SingleToPairwise — WMMA bf16-split GEMM, cp.async double-buffered.
// R16: tensor-core final projection (w_pair pre-split in gmem, B frags
//      loaded straight from global; tiny smem footprint).
// Split precision: x = hi + lo (bf16); A@B ~= Ah@Bh + Ah@Bl + Al@Bh
// RULE (R4-R9 lesson): NEVER pass __device__ globals as kernel args from host.
// ---------------------------------------------------------------------------

__device__ float g_gelu[1024 * 768];
__device__ __align__(16) __nv_bfloat16 g_pooled_h[1024 * 768];
__device__ __align__(16) __nv_bfloat16 g_pooled_l[1024 * 768];
__device__ __align__(16) __nv_bfloat16 g_wqk_h[8192 * 768];
__device__ __align__(16) __nv_bfloat16 g_wqk_l[8192 * 768];
__device__ __align__(16) __nv_bfloat16 g_wrel_h[4096 * 768];
__device__ __align__(16) __nv_bfloat16 g_wrel_l[4096 * 768];
__device__ __align__(16) __nv_bfloat16 g_rpf_h[1024 * 768];
__device__ __align__(16) __nv_bfloat16 g_rpf_l[1024 * 768];
__device__ __align__(16) __nv_bfloat16 g_qk_h[1024 * 8192];
__device__ __align__(16) __nv_bfloat16 g_qk_l[1024 * 8192];
__device__ __align__(16) __nv_bfloat16 g_re_h[1024 * 4096];
__device__ __align__(16) __nv_bfloat16 g_re_l[1024 * 4096];
__device__ __align__(16) __nv_bfloat16 g_wp_h[32 * 128];   // w_pair split [h][c]
__device__ __align__(16) __nv_bfloat16 g_wp_l[32 * 128];
__device__ float g_outer[1024 * 256];
__device__ float g_outer_part[6 * 1024 * 256];
__device__ float g_vq[32 * 1024];
__device__ float g_vk[32 * 1024];
__device__ float g_tq_hip[33554432];   // [hstore][i][p']
__device__ float g_tk_pj[33554432];    // [hstore][p'][j]  (transposed t_k)
__device__ float g_sim[33554432];      // [h][i][j]

// ---------------------------------------------------------------------------
__global__ void pool_gelu_kernel(const float* __restrict__ single)
{
    const int i = blockIdx.x;
    const int c = threadIdx.x;
    const float* p = single + ((size_t)i * 16) * 768 + c;
    float s = 0.f;
#pragma unroll
    for (int t = 0; t < 16; t++) s += p[t * 768];
    s *= 0.0625f;
    __nv_bfloat16 h = __float2bfloat16(s);
    g_pooled_h[i * 768 + c] = h;
    g_pooled_l[i * 768 + c] = __float2bfloat16(s - __bfloat162float(h));
    g_gelu[i * 768 + c] = 0.5f * s * (1.f + erff(s * 0.7071067811865475f));
}

// Split-convert all weight operands; destinations chosen IN DEVICE CODE.
__global__ void __launch_bounds__(256) convert_all(
    const float* __restrict__ wqk, const float* __restrict__ wrel,
    const float* __restrict__ rpf)
{
    long i = (long)blockIdx.x * 256 + threadIdx.x;
    const float* src;
    __nv_bfloat16 *hi, *lo;
    long o;
    if (i < 6291456L) {
        src = wqk; o = i; hi = g_wqk_h; lo = g_wqk_l;
    } else if (i < 9437184L) {
        src = wrel; o = i - 6291456L; hi = g_wrel_h; lo = g_wrel_l;
    } else {
        src = rpf + 544 * 768; o = i - 9437184L; hi = g_rpf_h; lo = g_rpf_l;
    }
    float v = src[o];
    __nv_bfloat16 h = __float2bfloat16(v);
    hi[o] = h;
    lo[o] = __float2bfloat16(v - __bfloat162float(h));
}

// w_pair [c][h] (128x32) -> split [h][c] in gmem
__global__ void __launch_bounds__(256) convert_wpair(const float* __restrict__ wp)
{
    int idx = blockIdx.x * 256 + threadIdx.x;   // 4096
    float v = wp[idx];
    int c = idx >> 5, h = idx & 31;
    __nv_bfloat16 hh = __float2bfloat16(v);
    g_wp_h[h * 128 + c] = hh;
    g_wp_l[h * 128 + c] = __float2bfloat16(v - __bfloat162float(hh));
}

// vq[h][p] = sum_d qb[h][d]*re[p][h*128+d]; vk likewise
__global__ void __launch_bounds__(256) bias_vec(const float* __restrict__ qk_bias)
{
    int idx = blockIdx.x * 256 + threadIdx.x;   // 32768
    int h = idx >> 10, p = idx & 1023;
    const float* qb = qk_bias + h * 128;
    const float* kb = qk_bias + 4096 + h * 128;
    int base = p * 4096 + h * 128;
    float sq = 0.f, sk = 0.f;
#pragma unroll 8
    for (int d = 0; d < 128; d++) {
        float r = __bfloat162float(g_re_h[base + d]) + __bfloat162float(g_re_l[base + d]);
        sq += qb[d] * r;
        sk += kb[d] * r;
    }
    g_vq[idx] = sq;
    g_vk[idx] = sk;
}

// ---------------------------------------------------------------------------
// cp.async helpers (sm_80 baseline PTX)
// ---------------------------------------------------------------------------
__device__ __forceinline__ void cp16(uint32_t dst, const void* src) {
    asm volatile("cp.async.cg.shared.global [%0], [%1], 16;" :: "r"(dst), "l"(src));
}
__device__ __forceinline__ void cp_commit() {
    asm volatile("cp.async.commit_group;" ::: "memory");
}
__device__ __forceinline__ void cp_wait1() {
    asm volatile("cp.async.wait_group 1;" ::: "memory");
}
__device__ __forceinline__ void cp_wait0() {
    asm volatile("cp.async.wait_group 0;" ::: "memory");
}

// ---------------------------------------------------------------------------
// WMMA bf16-split GEMM. 256 threads, 8 warps, warp tile 32x32.
// Block tile 64M x 128N, K-chunk 16, cp.async double buffer (2 x 18KB).
// ---------------------------------------------------------------------------
#define SMS 24
#define ROW_B 48
#define ST_A1 3072
#define ST_B0 6144
#define ST_B1 12288
#define STAGE_B 18432

__device__ __forceinline__ void stage_cp(uint32_t smbase, int stg,
    const __nv_bfloat16* __restrict__ Ah, const __nv_bfloat16* __restrict__ Al,
    int lda, int bm,
    const __nv_bfloat16* __restrict__ Bh, const __nv_bfloat16* __restrict__ Bl,
    int ldb, int bn, int kofs, int tid)
{
    const uint32_t s0 = smbase + stg * STAGE_B;
    {
        const int row = tid >> 2, q = tid & 3;
        const int chunk = q & 1, rg = q >> 1;
        const __nv_bfloat16* p = rg ? Al : Ah;
        const size_t off = (size_t)(bm + row) * lda + kofs + (chunk << 3);
        const uint32_t d = s0 + (rg ? ST_A1 : 0) + row * ROW_B + (chunk << 4);
        cp16(d, p + off);
    }
#pragma unroll
    for (int r = 0; r < 2; r++) {
        const int t = tid + (r << 8);
        const int row = t >> 2, q = t & 3;
        const int chunk = q & 1, rg = q >> 1;
        const __nv_bfloat16* p = rg ? Bl : Bh;
        const size_t off = (size_t)(bn + row) * ldb + kofs + (chunk << 3);
        const uint32_t d = s0 + (rg ? ST_B1 : ST_B0) + row * ROW_B + (chunk << 4);
        cp16(d, p + off);
    }
}

__global__ void __launch_bounds__(256) wmma_gemm(int mode,
    const float* __restrict__ X0)
{
    __shared__ __align__(16) char smbuf[2 * STAGE_B];   // 36864 B
    const uint32_t smbase = (uint32_t)__cvta_generic_to_shared(smbuf);

    const int tid = threadIdx.x;
    const int wid = tid >> 5, lane = tid & 31;
    const int wm = (wid & 1) << 5;
    const int wn = (wid >> 1) << 5;
    const int z = blockIdx.z;
    const int bm = blockIdx.y << 6, bn = blockIdx.x << 7;

    const __nv_bfloat16 *Ah, *Al, *Bh, *Bl;
    float* Cf = nullptr;
    __nv_bfloat16 *Ch = nullptr, *Cl = nullptr;
    const float* cb = nullptr;
    const float* rb = nullptr;
    int lda, ldb, ldc, K;
    switch (mode) {
    case 0:
        Ah = g_pooled_h; Al = g_pooled_l; lda = 768;
        Bh = g_wqk_h; Bl = g_wqk_l; ldb = 768;
        Ch = g_qk_h; Cl = g_qk_l; ldc = 8192; K = 768; break;
    case 1:
        Ah = g_rpf_h; Al = g_rpf_l; lda = 768;
        Bh = g_wrel_h; Bl = g_wrel_l; ldb = 768;
        Ch = g_re_h; Cl = g_re_l; ldc = 4096; K = 768; cb = X0; break;
    case 3:
        Ah = g_qk_h + z * 128; Al = g_qk_l + z * 128; lda = 8192;
        Bh = g_re_h + z * 128; Bl = g_re_l + z * 128; ldb = 4096;
        Cf = g_tq_hip + ((size_t)z << 20); ldc = 1024; K = 128; cb = g_vq + z * 1024; break;
    case 4:
        Ah = g_re_h + z * 128; Al = g_re_l + z * 128; lda = 4096;
        Bh = g_qk_h + 4096 + z * 128; Bl = g_qk_l + 4096 + z * 128; ldb = 8192;
        Cf = g_tk_pj + ((size_t)z << 20); ldc = 1024; K = 128; rb = g_vk + z * 1024; break;
    default:
        Ah = g_qk_h + z * 128; Al = g_qk_l + z * 128; lda = 8192;
        Bh = g_qk_h + 4096 + z * 128; Bl = g_qk_l + 4096 + z * 128; ldb = 8192;
        Cf = g_sim + ((size_t)z << 20); ldc = 1024; K = 128; break;
    }

    wmma::fragment<wmma::accumulator, 16, 16, 16, float> acc[2][2];
#pragma unroll
    for (int mf = 0; mf < 2; mf++)
#pragma unroll
        for (int nf = 0; nf < 2; nf++) wmma::fill_fragment(acc[mf][nf], 0.f);

    const int nK = K >> 4;

    stage_cp(smbase, 0, Ah, Al, lda, bm, Bh, Bl, ldb, bn, 0, tid);
    cp_commit();

    int cur = 0;
    for (int kc = 0; kc < nK; kc++) {
        const bool more = (kc + 1 < nK);
        if (more) {
            stage_cp(smbase, cur ^ 1, Ah, Al, lda, bm, Bh, Bl, ldb, bn,
                     (kc + 1) << 4, tid);
            cp_commit();
            cp_wait1();
        } else {
            cp_wait0();
        }
        __syncthreads();

        const __nv_bfloat16* sAh = (const __nv_bfloat16*)(smbuf + cur * STAGE_B);
        const __nv_bfloat16* sAl = (const __nv_bfloat16*)(smbuf + cur * STAGE_B + ST_A1);
        const __nv_bfloat16* sBh = (const __nv_bfloat16*)(smbuf + cur * STAGE_B + ST_B0);
        const __nv_bfloat16* sBl = (const __nv_bfloat16*)(smbuf + cur * STAGE_B + ST_B1);

        wmma::fragment<wmma::matrix_a, 16, 16, 16, __nv_bfloat16, wmma::row_major> ah[2], al[2];
        wmma::fragment<wmma::matrix_b, 16, 16, 16, __nv_bfloat16, wmma::col_major> bh[2], bl[2];
#pragma unroll
        for (int mf = 0; mf < 2; mf++) {
            wmma::load_matrix_sync(ah[mf], sAh + (wm + mf * 16) * SMS, SMS);
            wmma::load_matrix_sync(al[mf], sAl + (wm + mf * 16) * SMS, SMS);
        }
#pragma unroll
        for (int nf = 0; nf < 2; nf++) {
            wmma::load_matrix_sync(bh[nf], sBh + (wn + nf * 16) * SMS, SMS);
            wmma::load_matrix_sync(bl[nf], sBl + (wn + nf * 16) * SMS, SMS);
        }
#pragma unroll
        for (int mf = 0; mf < 2; mf++)
#pragma unroll
            for (int nf = 0; nf < 2; nf++) {
                wmma::mma_sync(acc[mf][nf], ah[mf], bh[nf], acc[mf][nf]);
                wmma::mma_sync(acc[mf][nf], ah[mf], bl[nf], acc[mf][nf]);
                wmma::mma_sync(acc[mf][nf], al[mf], bh[nf], acc[mf][nf]);
            }

        __syncthreads();
        cur ^= 1;
    }

    float* sc = (float*)smbuf + wid * 256;
    const int rr = lane >> 1;
    const int cc = (lane & 1) << 3;
#pragma unroll
    for (int mf = 0; mf < 2; mf++)
#pragma unroll
        for (int nf = 0; nf < 2; nf++) {
            wmma::store_matrix_sync(sc, acc[mf][nf], 16, wmma::mem_row_major);
            __syncwarp();
            const int row = bm + wm + mf * 16 + rr;
            const int col = bn + wn + nf * 16 + cc;
            float4 v0 = *(float4*)&sc[rr * 16 + cc];
            float4 v1 = *(float4*)&sc[rr * 16 + cc + 4];
            if (cb) {
                const float* b = cb + col;
                v0.x += b[0]; v0.y += b[1]; v0.z += b[2]; v0.w += b[3];
                v1.x += b[4]; v1.y += b[5]; v1.z += b[6]; v1.w += b[7];
            }
            if (rb) {
                float rv = rb[row];
                v0.x += rv; v0.y += rv; v0.z += rv; v0.w += rv;
                v1.x += rv; v1.y += rv; v1.z += rv; v1.w += rv;
            }
            if (Cf) {
                float* op = Cf + (size_t)row * ldc + col;
                *(float4*)op = v0;
                *((float4*)op + 1) = v1;
            } else {
                size_t o = (size_t)row * ldc + col;
                float vv[8] = {v0.x, v0.y, v0.z, v0.w, v1.x, v1.y, v1.z, v1.w};
#pragma unroll
                for (int c2 = 0; c2 < 8; c2 += 2) {
                    __nv_bfloat16 h0 = __float2bfloat16(vv[c2]);
                    __nv_bfloat16 h1 = __float2bfloat16(vv[c2 + 1]);
                    *(__nv_bfloat162*)&Ch[o + c2] = __halves2bfloat162(h0, h1);
                    *(__nv_bfloat162*)&Cl[o + c2] = __halves2bfloat162(
                        __float2bfloat16(vv[c2] - __bfloat162float(h0)),
                        __float2bfloat16(vv[c2 + 1] - __bfloat162float(h1)));
                }
            }
            __syncwarp();
        }
}

// ---------------------------------------------------------------------------
// fp32 SGEMM for outer, split-K (6 x 128) -> partials, then reduce.
// ---------------------------------------------------------------------------
__global__ void __launch_bounds__(256) sgemm_outer_splitk(const float* __restrict__ w_outer)
{
    const int kz = blockIdx.z;
    const float* A = g_gelu + kz * 128;
    const float* B = w_outer + kz * 128;
    float* C = g_outer_part + kz * 262144;
    const int lda = 768, ldb = 768, ldc = 256, K = 128;

    __shared__ float As[8][128];
    __shared__ float Bs[8][128];
    const int tid = threadIdx.x;
    const int bm = blockIdx.y << 7, bn = blockIdx.x << 7;
    const int lrow = tid >> 1;
    const int lk = (tid & 1) << 2;
    const int tr = (tid >> 4) << 3;
    const int tc = (tid & 15) << 3;

    float acc[8][8];
#pragma unroll
    for (int u = 0; u < 8; u++)
#pragma unroll
        for (int v = 0; v < 8; v++) acc[u][v] = 0.f;

    const float* Ap = A + (size_t)(bm + lrow) * lda + lk;
    const float* Bp = B + (size_t)(bn + lrow) * ldb + lk;

    for (int k0 = 0; k0 < K; k0 += 8) {
        float4 av = *(const float4*)(Ap + k0);
        float4 bv = *(const float4*)(Bp + k0);
        As[lk + 0][lrow] = av.x; As[lk + 1][lrow] = av.y;
        As[lk + 2][lrow] = av.z; As[lk + 3][lrow] = av.w;
        Bs[lk + 0][lrow] = bv.x; Bs[lk + 1][lrow] = bv.y;
        Bs[lk + 2][lrow] = bv.z; Bs[lk + 3][lrow] = bv.w;
        __syncthreads();
#pragma unroll
        for (int kk = 0; kk < 8; kk++) {
            float4 a0 = *(const float4*)&As[kk][tr];
            float4 a1 = *(const float4*)&As[kk][tr + 4];
            float4 b0 = *(const float4*)&Bs[kk][tc];
            float4 b1 = *(const float4*)&Bs[kk][tc + 4];
            float ar[8] = {a0.x, a0.y, a0.z, a0.w, a1.x, a1.y, a1.z, a1.w};
            float br[8] = {b0.x, b0.y, b0.z, b0.w, b1.x, b1.y, b1.z, b1.w};
#pragma unroll
            for (int u = 0; u < 8; u++)
#pragma unroll
                for (int v = 0; v < 8; v++) acc[u][v] += ar[u] * br[v];
        }
        __syncthreads();
    }
#pragma unroll
    for (int u = 0; u < 8; u++) {
        float* crow = C + (size_t)(bm + tr + u) * ldc + bn + tc;
        *(float4*)crow = make_float4(acc[u][0], acc[u][1], acc[u][2], acc[u][3]);
        *((float4*)crow + 1) = make_float4(acc[u][4], acc[u][5], acc[u][6], acc[u][7]);
    }
}

__global__ void __launch_bounds__(256) reduce_outer()
{
    int idx = blockIdx.x * 256 + threadIdx.x;
    float s = 0.f;
#pragma unroll
    for (int z = 0; z < 6; z++) s += g_outer_part[z * 262144 + idx];
    g_outer[idx] = s;
}

// ---------------------------------------------------------------------------
// Final fused kernel: gather -> split bf16 -> WMMA projection (+outer sum).
// smem: s_h[32*72] s_l[32*72] bf16, s_tq[32][64] f32 (aliased by epilogue
// scratch), s_bo[128] f32. w_pair fragments loaded directly from gmem.
// ---------------------------------------------------------------------------
#define SLD 72
#define G_SH 0
#define G_SL 4608
#define G_TQ 9216      // 8192 bytes; epilogue scratch aliases this
#define G_BO 17408
#define FSM_B 17920

__global__ void __launch_bounds__(256) final_kernel(
    const float* __restrict__ b_pair, float* __restrict__ out)
{
    __shared__ __align__(16) char fsm[FSM_B];
    __nv_bfloat16* s_h = (__nv_bfloat16*)(fsm + G_SH);
    __nv_bfloat16* s_l = (__nv_bfloat16*)(fsm + G_SL);
    float* s_tq = (float*)(fsm + G_TQ);
    float* s_bo = (float*)(fsm + G_BO);

    const int i = blockIdx.y;
    const int j0 = blockIdx.x << 6;
    const int tid = threadIdx.x;
    const int wid = tid >> 5, lane = tid & 31;

    if (tid < 128) s_bo[tid] = b_pair[tid] + g_outer[i * 256 + tid];

    const int F0 = 18432 + (j0 << 5);
    const int p0 = F0 / 33 - 544;
    for (int idx = tid; idx < 2048; idx += 256) {
        int hs = idx >> 6, x = idx & 63;
        s_tq[hs * 64 + x] = g_tq_hip[((size_t)hs << 20) + ((size_t)i << 10) + p0 + x];
    }
    __syncthreads();

    const int M0 = 18432 + (i << 5);
    for (int idx = tid; idx < 2048; idx += 256) {
        int h = idx >> 6, jj = idx & 63;
        float sv = g_sim[((size_t)h << 20) + ((size_t)i << 10) + (j0 + jj)];
        int m = F0 + (jj << 5) + h;
        int P = m / 33, r = m - P * 33;
        float tq = (r == 0) ? 0.f : s_tq[(r - 1) * 64 + (P - 544 - p0)];
        int mi = M0 + h;
        int Pi = mi / 33, ri = mi - Pi * 33;
        float tk = (ri == 0) ? 0.f
            : g_tk_pj[((size_t)(ri - 1) << 20) + ((size_t)(Pi - 544) << 10) + j0 + jj];
        sv += 0.5f * (tq + tk);
        __nv_bfloat16 hh = __float2bfloat16(sv);
        s_h[h * SLD + jj] = hh;
        s_l[h * SLD + jj] = __float2bfloat16(sv - __bfloat162float(hh));
    }
    __syncthreads();   // s split ready; s_tq dead (scratch aliases it)

    // out_tile[jj][c] = sum_h s[h][jj]*wp[h][c]  (64x128, K=32)
    const int wm2 = (wid & 3) << 4;     // jj group
    const int wn2 = (wid >> 2) << 6;    // c half
    wmma::fragment<wmma::accumulator, 16, 16, 16, float> acc2[4];
#pragma unroll
    for (int nf = 0; nf < 4; nf++) wmma::fill_fragment(acc2[nf], 0.f);

#pragma unroll
    for (int ks = 0; ks < 2; ks++) {
        const int kb = ks << 4;
        wmma::fragment<wmma::matrix_a, 16, 16, 16, __nv_bfloat16, wmma::col_major> a_h, a_l;
        wmma::load_matrix_sync(a_h, s_h + kb * SLD + wm2, SLD);
        wmma::load_matrix_sync(a_l, s_l + kb * SLD + wm2, SLD);
#pragma unroll
        for (int nf = 0; nf < 4; nf++) {
            wmma::fragment<wmma::matrix_b, 16, 16, 16, __nv_bfloat16, wmma::row_major> b_h, b_l;
            wmma::load_matrix_sync(b_h, g_wp_h + kb * 128 + wn2 + nf * 16, 128);
            wmma::load_matrix_sync(b_l, g_wp_l + kb * 128 + wn2 + nf * 16, 128);
            wmma::mma_sync(acc2[nf], a_h, b_h, acc2[nf]);
            wmma::mma_sync(acc2[nf], a_h, b_l, acc2[nf]);
            wmma::mma_sync(acc2[nf], a_l, b_h, acc2[nf]);
        }
    }

    // epilogue: per-warp scratch aliases s_tq (8 warps x 256 f32 = 8192 B)
    float* sc = (float*)(fsm + G_TQ) + wid * 256;
    const int rr = lane >> 1;
    const int cc = (lane & 1) << 3;
    const int j = j0 + wm2 + rr;
#pragma unroll
    for (int nf = 0; nf < 4; nf++) {
        wmma::store_matrix_sync(sc, acc2[nf], 16, wmma::mem_row_major);
        __syncwarp();
        const int c = wn2 + nf * 16 + cc;
        float4 v0 = *(float4*)&sc[rr * 16 + cc];
        float4 v1 = *(float4*)&sc[rr * 16 + cc + 4];
        const float* okp = g_outer + j * 256 + 128 + c;
        v0.x += s_bo[c + 0] + okp[0]; v0.y += s_bo[c + 1] + okp[1];
        v0.z += s_bo[c + 2] + okp[2]; v0.w += s_bo[c + 3] + okp[3];
        v1.x += s_bo[c + 4] + okp[4]; v1.y += s_bo[c + 5] + okp[5];
        v1.z += s_bo[c + 6] + okp[6]; v1.w += s_bo[c + 7] + okp[7];
        float* op = out + ((((size_t)i << 10) + j) << 7) + c;
        *(float4*)op = v0;
        *((float4*)op + 1) = v1;
        __syncwarp();
    }
}

// ---------------------------------------------------------------------------
extern "C" void kernel_launch(void* const* d_in, const int* in_sizes, int n_in,
                              void* d_out, int out_size)
{
    (void)in_sizes; (void)n_in; (void)out_size;
    const float* single        = (const float*)d_in[0];
    const float* rel_pos_feats = (const float*)d_in[1];
    const float* w_qk          = (const float*)d_in[2];
    const float* w_outer       = (const float*)d_in[3];
    const float* w_pair        = (const float*)d_in[4];
    const float* b_pair        = (const float*)d_in[5];
    const float* w_rel         = (const float*)d_in[6];
    const float* b_rel         = (const float*)d_in[7];
    const float* qk_bias       = (const float*)d_in[8];
    float* out = (float*)d_out;

    pool_gelu_kernel<<<1024, 768>>>(single);
    convert_all<<<39936, 256>>>(w_qk, w_rel, rel_pos_feats);
    convert_wpair<<<16, 256>>>(w_pair);

    wmma_gemm<<<dim3(64, 16, 1), 256>>>(0, nullptr);   // qk
    wmma_gemm<<<dim3(32, 16, 1), 256>>>(1, b_rel);     // rel_enc
    sgemm_outer_splitk<<<dim3(2, 8, 6), 256>>>(w_outer);
    reduce_outer<<<1024, 256>>>();
    bias_vec<<<128, 256>>>(qk_bias);
    wmma_gemm<<<dim3(8, 16, 32), 256>>>(3, nullptr);   // t_q
    wmma_gemm<<<dim3(8, 16, 32), 256>>>(4, nullptr);   // t_k (transposed out)
    wmma_gemm<<<dim3(8, 16, 32), 256>>>(5, nullptr);   // sim
    final_kernel<<<dim3(16, 1024, 1), 256>>>(b_pair, out);
}